// round 15
// baseline (speedup 1.0000x reference)
#include <cuda_runtime.h>
#include <cuda_bf16.h>
#include <math.h>
#include <stdint.h>

#define N_NODES 8192
#define DIN     512
#define DOUT    256
#define MAXN    512
#define AGRID   1024   // persistent attn grid

// ---------------------------------------------------------------------------
// Device scratch (globals: allocation-free per harness rules)
// ---------------------------------------------------------------------------
__device__ float g_h[(size_t)N_NODES * DOUT];   // 8 MB
__device__ float g_g1[N_NODES];
__device__ float g_g2[N_NODES];
__device__ __align__(16) __nv_bfloat16 g_ahi[(size_t)N_NODES * DIN];  // 8 MB
__device__ __align__(16) __nv_bfloat16 g_alo[(size_t)N_NODES * DIN];  // 8 MB
__device__ __align__(16) __nv_bfloat16 g_whi[(size_t)DOUT * DIN];     // W^T [n][k]
__device__ __align__(16) __nv_bfloat16 g_wlo[(size_t)DOUT * DIN];
__device__ int g_nbr[(size_t)N_NODES * MAXN];   // neighbor lists (sparse writes)
__device__ int g_deg[N_NODES];

// ---------------------------------------------------------------------------
// PTX helpers
// ---------------------------------------------------------------------------
__device__ __forceinline__ uint32_t smem_u32(const void* p) {
    uint32_t a;
    asm("{ .reg .u64 t; cvta.to.shared.u64 t, %1; cvt.u32.u64 %0, t; }"
        : "=r"(a) : "l"(p));
    return a;
}
__device__ __forceinline__ void cp16(uint32_t dst, const void* src) {
    asm volatile("cp.async.ca.shared.global [%0], [%1], 16;"
                 :: "r"(dst), "l"(src) : "memory");
}
#define CP_COMMIT() asm volatile("cp.async.commit_group;" ::: "memory")
#define CP_WAIT(n)  asm volatile("cp.async.wait_group %0;" :: "n"(n) : "memory")

__device__ __forceinline__ uint32_t lds32(uint32_t addr) {
    uint32_t v;
    asm volatile("ld.shared.b32 %0, [%1];" : "=r"(v) : "r"(addr));
    return v;
}
__device__ __forceinline__ void mma16816(float* d, const uint32_t* a,
                                         const uint32_t* b) {
    asm volatile(
        "mma.sync.aligned.m16n8k16.row.col.f32.bf16.bf16.f32 "
        "{%0,%1,%2,%3}, {%4,%5,%6,%7}, {%8,%9}, {%0,%1,%2,%3};"
        : "+f"(d[0]), "+f"(d[1]), "+f"(d[2]), "+f"(d[3])
        : "r"(a[0]), "r"(a[1]), "r"(a[2]), "r"(a[3]), "r"(b[0]), "r"(b[1]));
}
__device__ __forceinline__ unsigned short bf16b(float v) {
    __nv_bfloat16 h = __float2bfloat16_rn(v);
    return *reinterpret_cast<unsigned short*>(&h);
}

// ---------------------------------------------------------------------------
// Prep A: elu(x) -> bf16 hi/lo, row-major [8192][512].
// ---------------------------------------------------------------------------
__global__ void __launch_bounds__(256)
prep_a_kernel(const float* __restrict__ X)
{
    int T = blockIdx.x * 256 + threadIdx.x;
    int m  = T >> 6;
    int k0 = (T & 63) << 3;

    float4 v0 = *(const float4*)(X + (size_t)m * DIN + k0);
    float4 v1 = *(const float4*)(X + (size_t)m * DIN + k0 + 4);
    float f[8] = {v0.x, v0.y, v0.z, v0.w, v1.x, v1.y, v1.z, v1.w};

    unsigned short hs[8], ls[8];
#pragma unroll
    for (int i = 0; i < 8; i++) {
        float v = f[i] > 0.f ? f[i] : expm1f(f[i]);
        hs[i] = bf16b(v);
        float hf = __uint_as_float((uint32_t)hs[i] << 16);
        ls[i] = bf16b(v - hf);
    }
    uint4 ph, pl;
    ph.x = hs[0] | ((uint32_t)hs[1] << 16); ph.y = hs[2] | ((uint32_t)hs[3] << 16);
    ph.z = hs[4] | ((uint32_t)hs[5] << 16); ph.w = hs[6] | ((uint32_t)hs[7] << 16);
    pl.x = ls[0] | ((uint32_t)ls[1] << 16); pl.y = ls[2] | ((uint32_t)ls[3] << 16);
    pl.z = ls[4] | ((uint32_t)ls[5] << 16); pl.w = ls[6] | ((uint32_t)ls[7] << 16);

    *(uint4*)(g_ahi + (size_t)m * DIN + k0) = ph;
    *(uint4*)(g_alo + (size_t)m * DIN + k0) = pl;
}

// ---------------------------------------------------------------------------
// Prep W: W[512,256] -> W^T hi/lo bf16 [256 n][512 k]; init g1/g2 to biases.
// ---------------------------------------------------------------------------
__global__ void __launch_bounds__(256)
prep_w_kernel(const float* __restrict__ W,
              const float* __restrict__ a1b, const float* __restrict__ a2b)
{
    int T = blockIdx.x * 256 + threadIdx.x;
    if (T < N_NODES) {
        g_g1[T] = a1b[0];
        g_g2[T] = a2b[0];
    }
    int n  = T >> 6;
    int k0 = (T & 63) << 3;

    unsigned short hs[8], ls[8];
#pragma unroll
    for (int i = 0; i < 8; i++) {
        float v = W[(size_t)(k0 + i) * DOUT + n];
        hs[i] = bf16b(v);
        float hf = __uint_as_float((uint32_t)hs[i] << 16);
        ls[i] = bf16b(v - hf);
    }
    uint4 ph, pl;
    ph.x = hs[0] | ((uint32_t)hs[1] << 16); ph.y = hs[2] | ((uint32_t)hs[3] << 16);
    ph.z = hs[4] | ((uint32_t)hs[5] << 16); ph.w = hs[6] | ((uint32_t)hs[7] << 16);
    pl.x = ls[0] | ((uint32_t)ls[1] << 16); pl.y = ls[2] | ((uint32_t)ls[3] << 16);
    pl.z = ls[4] | ((uint32_t)ls[5] << 16); pl.w = ls[6] | ((uint32_t)ls[7] << 16);

    *(uint4*)(g_whi + (size_t)n * DIN + k0) = ph;
    *(uint4*)(g_wlo + (size_t)n * DIN + k0) = pl;
}

// ---------------------------------------------------------------------------
// mma.sync GEMM (R7 version): h = A@W^T + b with 3-term bf16 split.
// Fires launch_dependents at entry so the persistent attn kernel's scan
// phase overlaps the mainloop.
// ---------------------------------------------------------------------------
#define SA 40
#define STG 10240
#define N_STAGES 48

__global__ void __launch_bounds__(256)
gemm_mma_kernel(const float* __restrict__ b,
                const float* __restrict__ a1w, const float* __restrict__ a2w)
{
    asm volatile("griddepcontrol.launch_dependents;" ::: "memory");

    __shared__ __align__(16) unsigned char sm[4 * STG];

    const int t    = threadIdx.x;
    const int wid  = t >> 5;
    const int lane = t & 31;
    const int g    = lane >> 2;
    const int tl   = lane & 3;
    const int wm0  = (wid >> 2) * 64;
    const int wn0  = (wid & 3) * 32;
    const int m0   = blockIdx.y * 128;
    const int n0   = blockIdx.x * 128;

    const uint32_t sbase = smem_u32(sm);

    float d[4][4][4];
#pragma unroll
    for (int mt = 0; mt < 4; mt++)
#pragma unroll
        for (int nt = 0; nt < 4; nt++)
#pragma unroll
            for (int i = 0; i < 4; i++) d[mt][nt][i] = 0.f;

    const int crow0 = t >> 2;
    const int crow1 = crow0 + 64;
    const int cc    = (t & 3) << 3;

    auto load_stage = [&](int s) {
        const int term = s >> 4;
        const int kt   = (s & 15) << 5;
        const __nv_bfloat16* aS = (term == 1) ? g_alo : g_ahi;
        const __nv_bfloat16* bS = (term == 2) ? g_wlo : g_whi;
        const int buf = s & 1;
        uint32_t aBase = sbase + buf * STG;
        uint32_t bBase = sbase + 2 * STG + buf * STG;
        cp16(aBase + crow0 * (SA * 2) + cc * 2,
             aS + (size_t)(m0 + crow0) * DIN + kt + cc);
        cp16(aBase + crow1 * (SA * 2) + cc * 2,
             aS + (size_t)(m0 + crow1) * DIN + kt + cc);
        cp16(bBase + crow0 * (SA * 2) + cc * 2,
             bS + (size_t)(n0 + crow0) * DIN + kt + cc);
        cp16(bBase + crow1 * (SA * 2) + cc * 2,
             bS + (size_t)(n0 + crow1) * DIN + kt + cc);
    };

    load_stage(0);
    CP_COMMIT();

    for (int s = 0; s < N_STAGES; s++) {
        if (s + 1 < N_STAGES) {
            load_stage(s + 1);
            CP_COMMIT();
            CP_WAIT(1);
        } else {
            CP_WAIT(0);
        }
        __syncthreads();

        const int buf = s & 1;
        const uint32_t aT = sbase + buf * STG + (wm0 + g) * (SA * 2) + tl * 4;
        const uint32_t bT = sbase + 2 * STG + buf * STG + (wn0 + g) * (SA * 2) + tl * 4;

#pragma unroll
        for (int kh = 0; kh < 2; kh++) {
            const uint32_t ko = kh * 32;
            uint32_t a[4][4], bb[4][2];
#pragma unroll
            for (int mt = 0; mt < 4; mt++) {
                uint32_t r = aT + mt * (16 * SA * 2) + ko;
                a[mt][0] = lds32(r);
                a[mt][1] = lds32(r + 8 * SA * 2);
                a[mt][2] = lds32(r + 16);
                a[mt][3] = lds32(r + 8 * SA * 2 + 16);
            }
#pragma unroll
            for (int nt = 0; nt < 4; nt++) {
                uint32_t r = bT + nt * (8 * SA * 2) + ko;
                bb[nt][0] = lds32(r);
                bb[nt][1] = lds32(r + 16);
            }
#pragma unroll
            for (int mt = 0; mt < 4; mt++)
#pragma unroll
                for (int nt = 0; nt < 4; nt++)
                    mma16816(d[mt][nt], a[mt], bb[nt]);
        }
        __syncthreads();
    }

    float2 bias[4], w1c[4], w2c[4];
#pragma unroll
    for (int nt = 0; nt < 4; nt++) {
        int col = n0 + wn0 + nt * 8 + 2 * tl;
        bias[nt] = *(const float2*)(b + col);
        w1c[nt]  = *(const float2*)(a1w + col);
        w2c[nt]  = *(const float2*)(a2w + col);
    }

#pragma unroll
    for (int mt = 0; mt < 4; mt++) {
        int row0 = m0 + wm0 + mt * 16 + g;
        float s1r0 = 0.f, s2r0 = 0.f, s1r1 = 0.f, s2r1 = 0.f;
#pragma unroll
        for (int nt = 0; nt < 4; nt++) {
            int col = n0 + wn0 + nt * 8 + 2 * tl;
            float2 v0 = make_float2(d[mt][nt][0] + bias[nt].x,
                                    d[mt][nt][1] + bias[nt].y);
            float2 v1 = make_float2(d[mt][nt][2] + bias[nt].x,
                                    d[mt][nt][3] + bias[nt].y);
            *(float2*)(g_h + (size_t)row0 * DOUT + col) = v0;
            *(float2*)(g_h + (size_t)(row0 + 8) * DOUT + col) = v1;
            s1r0 = fmaf(v0.x, w1c[nt].x, fmaf(v0.y, w1c[nt].y, s1r0));
            s2r0 = fmaf(v0.x, w2c[nt].x, fmaf(v0.y, w2c[nt].y, s2r0));
            s1r1 = fmaf(v1.x, w1c[nt].x, fmaf(v1.y, w1c[nt].y, s1r1));
            s2r1 = fmaf(v1.x, w2c[nt].x, fmaf(v1.y, w2c[nt].y, s2r1));
        }
        atomicAdd(&g_g1[row0], s1r0);
        atomicAdd(&g_g2[row0], s2r0);
        atomicAdd(&g_g1[row0 + 8], s1r1);
        atomicAdd(&g_g2[row0 + 8], s2r1);
    }
}

// ---------------------------------------------------------------------------
// Persistent attn kernel (PDL secondary).
// Phase 1: each block scans N_NODES/AGRID adjacency rows into gmem neighbor
//          lists (depends only on adj -> overlaps ALL of preps+GEMM).
// griddepcontrol.wait
// Phase 2: per row: scores from g1/g2, warp-0 softmax, gather h, write out.
// ---------------------------------------------------------------------------
__global__ void __launch_bounds__(256)
attn_kernel(const float* __restrict__ adj, float* __restrict__ out)
{
    __shared__ int   s_idx[MAXN];
    __shared__ float s_e[MAXN];
    __shared__ int   s_cnt;
    __shared__ float s_inv;

    const int t = threadIdx.x;

    // ---- phase 1: scan assigned rows into gmem lists ----
    for (int r = blockIdx.x; r < N_NODES; r += AGRID) {
        if (t == 0) s_cnt = 0;
        __syncthreads();

        const float4* row = (const float4*)(adj + (size_t)r * N_NODES);
        int* nbr = g_nbr + (size_t)r * MAXN;
#pragma unroll
        for (int u = 0; u < 8; u++) {
            int f = t + u * 256;
            float4 v = row[f];
            int jb = f << 2;
            if (v.x > 0.f) { int p = atomicAdd(&s_cnt, 1); if (p < MAXN) nbr[p] = jb + 0; }
            if (v.y > 0.f) { int p = atomicAdd(&s_cnt, 1); if (p < MAXN) nbr[p] = jb + 1; }
            if (v.z > 0.f) { int p = atomicAdd(&s_cnt, 1); if (p < MAXN) nbr[p] = jb + 2; }
            if (v.w > 0.f) { int p = atomicAdd(&s_cnt, 1); if (p < MAXN) nbr[p] = jb + 3; }
        }
        __syncthreads();
        if (t == 0) g_deg[r] = s_cnt < MAXN ? s_cnt : MAXN;
        __syncthreads();
    }

    // ---- wait for the GEMM's g_h / g_g1 / g_g2 ----
    asm volatile("griddepcontrol.wait;" ::: "memory");

    // ---- phase 2: softmax + aggregation per assigned row ----
    for (int r = blockIdx.x; r < N_NODES; r += AGRID) {
        const int cnt = g_deg[r];

        if (cnt == 0) {
            float acc = 0.f;
            for (int q = 0; q < N_NODES; q++) acc += g_h[(size_t)q * DOUT + t];
            out[(size_t)r * DOUT + t] = acc * (1.f / (float)N_NODES);
            continue;   // block-uniform branch
        }

        const float g2i = g_g2[r];
        const int* nbr = g_nbr + (size_t)r * MAXN;
        for (int k = t; k < cnt; k += 256) {
            int j = nbr[k];
            s_idx[k] = j;
            float s = g2i + g_g1[j];
            s_e[k] = s > 0.f ? s : 0.2f * s;
        }
        __syncthreads();

        if (t < 32) {
            float m = -INFINITY;
            for (int k = t; k < cnt; k += 32) m = fmaxf(m, s_e[k]);
#pragma unroll
            for (int o = 16; o; o >>= 1) m = fmaxf(m, __shfl_xor_sync(0xffffffffu, m, o));
            float ssum = 0.f;
            for (int k = t; k < cnt; k += 32) {
                float w = __expf(s_e[k] - m);
                s_e[k] = w;
                ssum += w;
            }
#pragma unroll
            for (int o = 16; o; o >>= 1) ssum += __shfl_xor_sync(0xffffffffu, ssum, o);
            if (t == 0) s_inv = 1.f / ssum;
        }
        __syncthreads();

        const float inv = s_inv;
        float a0 = 0.f, a1 = 0.f, a2 = 0.f, a3 = 0.f;
        int k = 0;
        for (; k + 4 <= cnt; k += 4) {
            a0 = fmaf(s_e[k + 0], g_h[(size_t)s_idx[k + 0] * DOUT + t], a0);
            a1 = fmaf(s_e[k + 1], g_h[(size_t)s_idx[k + 1] * DOUT + t], a1);
            a2 = fmaf(s_e[k + 2], g_h[(size_t)s_idx[k + 2] * DOUT + t], a2);
            a3 = fmaf(s_e[k + 3], g_h[(size_t)s_idx[k + 3] * DOUT + t], a3);
        }
        for (; k < cnt; k++)
            a0 = fmaf(s_e[k], g_h[(size_t)s_idx[k] * DOUT + t], a0);

        out[(size_t)r * DOUT + t] = (a0 + a1 + a2 + a3) * inv;
        __syncthreads();
    }
}

// ---------------------------------------------------------------------------
extern "C" void kernel_launch(void* const* d_in, const int* in_sizes, int n_in,
                              void* d_out, int out_size)
{
    const float* x   = (const float*)d_in[0];   // [8192, 512]
    const float* adj = (const float*)d_in[1];   // [8192, 8192]
    const float* W1  = (const float*)d_in[2];   // [512, 256]
    const float* b1  = (const float*)d_in[3];   // [256]
    const float* a1w = (const float*)d_in[4];   // [256]
    const float* a1b = (const float*)d_in[5];   // scalar
    const float* a2w = (const float*)d_in[6];   // [256]
    const float* a2b = (const float*)d_in[7];   // scalar
    float* out = (float*)d_out;                 // [8192, 256]

    prep_a_kernel<<<2048, 256>>>(x);
    prep_w_kernel<<<64, 256>>>(W1, a1b, a2b);
    dim3 gg(DOUT / 128, N_NODES / 128);         // (2, 64)
    gemm_mma_kernel<<<gg, 256>>>(b1, a1w, a2w);

    // persistent attn via PDL: phase-1 scan overlaps preps+GEMM entirely.
    cudaLaunchConfig_t cfg = {};
    cfg.gridDim  = dim3(AGRID, 1, 1);
    cfg.blockDim = dim3(256, 1, 1);
    cfg.dynamicSmemBytes = 0;
    cfg.stream = 0;
    cudaLaunchAttribute attrs[1];
    attrs[0].id = cudaLaunchAttributeProgrammaticStreamSerialization;
    attrs[0].val.programmaticStreamSerializationAllowed = 1;
    cfg.attrs = attrs;
    cfg.numAttrs = 1;
    cudaLaunchKernelEx(&cfg, attn_kernel, adj, out);
}

// round 16
// speedup vs baseline: 1.3506x; 1.3506x over previous
#include <cuda_runtime.h>
#include <cuda_bf16.h>
#include <math.h>
#include <stdint.h>

#define N_NODES 8192
#define DIN     512
#define DOUT    256
#define MAXN    512

// ---------------------------------------------------------------------------
// Device scratch (globals: allocation-free per harness rules)
// ---------------------------------------------------------------------------
__device__ float g_h[(size_t)N_NODES * DOUT];   // 8 MB
__device__ float g_g1[N_NODES];
__device__ float g_g2[N_NODES];
__device__ __align__(16) __nv_bfloat16 g_ahi[(size_t)N_NODES * DIN];  // 8 MB
__device__ __align__(16) __nv_bfloat16 g_alo[(size_t)N_NODES * DIN];  // 8 MB
__device__ __align__(16) __nv_bfloat16 g_whi[(size_t)DOUT * DIN];     // W^T [n][k]
__device__ __align__(16) __nv_bfloat16 g_wlo[(size_t)DOUT * DIN];

// ---------------------------------------------------------------------------
// PTX helpers
// ---------------------------------------------------------------------------
__device__ __forceinline__ uint32_t smem_u32(const void* p) {
    uint32_t a;
    asm("{ .reg .u64 t; cvta.to.shared.u64 t, %1; cvt.u32.u64 %0, t; }"
        : "=r"(a) : "l"(p));
    return a;
}
__device__ __forceinline__ void cp16(uint32_t dst, const void* src) {
    asm volatile("cp.async.ca.shared.global [%0], [%1], 16;"
                 :: "r"(dst), "l"(src) : "memory");
}
#define CP_COMMIT() asm volatile("cp.async.commit_group;" ::: "memory")
#define CP_WAIT(n)  asm volatile("cp.async.wait_group %0;" :: "n"(n) : "memory")

__device__ __forceinline__ uint32_t lds32(uint32_t addr) {
    uint32_t v;
    asm volatile("ld.shared.b32 %0, [%1];" : "=r"(v) : "r"(addr));
    return v;
}
__device__ __forceinline__ void mma16816(float* d, const uint32_t* a,
                                         const uint32_t* b) {
    asm volatile(
        "mma.sync.aligned.m16n8k16.row.col.f32.bf16.bf16.f32 "
        "{%0,%1,%2,%3}, {%4,%5,%6,%7}, {%8,%9}, {%0,%1,%2,%3};"
        : "+f"(d[0]), "+f"(d[1]), "+f"(d[2]), "+f"(d[3])
        : "r"(a[0]), "r"(a[1]), "r"(a[2]), "r"(a[3]), "r"(b[0]), "r"(b[1]));
}
__device__ __forceinline__ unsigned short bf16b(float v) {
    __nv_bfloat16 h = __float2bfloat16_rn(v);
    return *reinterpret_cast<unsigned short*>(&h);
}

// ---------------------------------------------------------------------------
// Combined prep: blocks [0,2048) convert elu(x)->bf16 hi/lo;
// blocks [2048,2112) convert W->W^T hi/lo and init g1/g2 to biases.
// ---------------------------------------------------------------------------
#define PREP_A_BLOCKS 2048
#define PREP_BLOCKS   (PREP_A_BLOCKS + 64)

__global__ void __launch_bounds__(256)
prep_kernel(const float* __restrict__ X, const float* __restrict__ W,
            const float* __restrict__ a1b, const float* __restrict__ a2b)
{
    if (blockIdx.x < PREP_A_BLOCKS) {
        int T = blockIdx.x * 256 + threadIdx.x;
        int m  = T >> 6;
        int k0 = (T & 63) << 3;

        float4 v0 = *(const float4*)(X + (size_t)m * DIN + k0);
        float4 v1 = *(const float4*)(X + (size_t)m * DIN + k0 + 4);
        float f[8] = {v0.x, v0.y, v0.z, v0.w, v1.x, v1.y, v1.z, v1.w};

        unsigned short hs[8], ls[8];
#pragma unroll
        for (int i = 0; i < 8; i++) {
            float v = f[i] > 0.f ? f[i] : expm1f(f[i]);
            hs[i] = bf16b(v);
            float hf = __uint_as_float((uint32_t)hs[i] << 16);
            ls[i] = bf16b(v - hf);
        }
        uint4 ph, pl;
        ph.x = hs[0] | ((uint32_t)hs[1] << 16); ph.y = hs[2] | ((uint32_t)hs[3] << 16);
        ph.z = hs[4] | ((uint32_t)hs[5] << 16); ph.w = hs[6] | ((uint32_t)hs[7] << 16);
        pl.x = ls[0] | ((uint32_t)ls[1] << 16); pl.y = ls[2] | ((uint32_t)ls[3] << 16);
        pl.z = ls[4] | ((uint32_t)ls[5] << 16); pl.w = ls[6] | ((uint32_t)ls[7] << 16);

        *(uint4*)(g_ahi + (size_t)m * DIN + k0) = ph;
        *(uint4*)(g_alo + (size_t)m * DIN + k0) = pl;
    } else {
        int T = (blockIdx.x - PREP_A_BLOCKS) * 256 + threadIdx.x;   // 0..16383
        if (T < N_NODES) {
            g_g1[T] = a1b[0];
            g_g2[T] = a2b[0];
        }
        int n  = T >> 6;
        int k0 = (T & 63) << 3;

        unsigned short hs[8], ls[8];
#pragma unroll
        for (int i = 0; i < 8; i++) {
            float v = W[(size_t)(k0 + i) * DOUT + n];
            hs[i] = bf16b(v);
            float hf = __uint_as_float((uint32_t)hs[i] << 16);
            ls[i] = bf16b(v - hf);
        }
        uint4 ph, pl;
        ph.x = hs[0] | ((uint32_t)hs[1] << 16); ph.y = hs[2] | ((uint32_t)hs[3] << 16);
        ph.z = hs[4] | ((uint32_t)hs[5] << 16); ph.w = hs[6] | ((uint32_t)hs[7] << 16);
        pl.x = ls[0] | ((uint32_t)ls[1] << 16); pl.y = ls[2] | ((uint32_t)ls[3] << 16);
        pl.z = ls[4] | ((uint32_t)ls[5] << 16); pl.w = ls[6] | ((uint32_t)ls[7] << 16);

        *(uint4*)(g_whi + (size_t)n * DIN + k0) = ph;
        *(uint4*)(g_wlo + (size_t)n * DIN + k0) = pl;
    }
}

// ---------------------------------------------------------------------------
// mma.sync GEMM: h = A@W^T + b with 3-term bf16 split.
// CTA 128x128, 8 warps, warp tile 64x32, BK=32, 4-stage cp.async pipeline
// (dynamic smem, buffers s%4). Fires launch_dependents at entry (PDL).
// Epilogue accumulates g1/g2 via atomics.
// ---------------------------------------------------------------------------
#define SA 40
#define TILE_B  10240                 // 128 rows x 40 bf16
#define STAGE_B (2 * TILE_B)          // A + B per stage = 20480
#define GEMM_SMEM (4 * STAGE_B)       // 81920
#define N_STAGES 48

__global__ void __launch_bounds__(256)
gemm_mma_kernel(const float* __restrict__ b,
                const float* __restrict__ a1w, const float* __restrict__ a2w)
{
    asm volatile("griddepcontrol.launch_dependents;" ::: "memory");

    extern __shared__ __align__(16) unsigned char sm[];

    const int t    = threadIdx.x;
    const int wid  = t >> 5;
    const int lane = t & 31;
    const int g    = lane >> 2;
    const int tl   = lane & 3;
    const int wm0  = (wid >> 2) * 64;
    const int wn0  = (wid & 3) * 32;
    const int m0   = blockIdx.y * 128;
    const int n0   = blockIdx.x * 128;

    const uint32_t sbase = smem_u32(sm);

    float d[4][4][4];
#pragma unroll
    for (int mt = 0; mt < 4; mt++)
#pragma unroll
        for (int nt = 0; nt < 4; nt++)
#pragma unroll
            for (int i = 0; i < 4; i++) d[mt][nt][i] = 0.f;

    const int crow0 = t >> 2;
    const int crow1 = crow0 + 64;
    const int cc    = (t & 3) << 3;

    auto load_stage = [&](int s) {
        const int term = s >> 4;
        const int kt   = (s & 15) << 5;
        const __nv_bfloat16* aS = (term == 1) ? g_alo : g_ahi;
        const __nv_bfloat16* bS = (term == 2) ? g_wlo : g_whi;
        const uint32_t aBase = sbase + (s & 3) * STAGE_B;
        const uint32_t bBase = aBase + TILE_B;
        cp16(aBase + crow0 * (SA * 2) + cc * 2,
             aS + (size_t)(m0 + crow0) * DIN + kt + cc);
        cp16(aBase + crow1 * (SA * 2) + cc * 2,
             aS + (size_t)(m0 + crow1) * DIN + kt + cc);
        cp16(bBase + crow0 * (SA * 2) + cc * 2,
             bS + (size_t)(n0 + crow0) * DIN + kt + cc);
        cp16(bBase + crow1 * (SA * 2) + cc * 2,
             bS + (size_t)(n0 + crow1) * DIN + kt + cc);
    };

    load_stage(0); CP_COMMIT();
    load_stage(1); CP_COMMIT();
    load_stage(2); CP_COMMIT();

    for (int s = 0; s < N_STAGES; s++) {
        if (s + 3 < N_STAGES) {
            load_stage(s + 3);
            CP_COMMIT();
            CP_WAIT(3);
        } else if (s + 2 < N_STAGES) {
            CP_WAIT(2);
        } else if (s + 1 < N_STAGES) {
            CP_WAIT(1);
        } else {
            CP_WAIT(0);
        }
        __syncthreads();

        const uint32_t aBase = sbase + (s & 3) * STAGE_B;
        const uint32_t aT = aBase + (wm0 + g) * (SA * 2) + tl * 4;
        const uint32_t bT = aBase + TILE_B + (wn0 + g) * (SA * 2) + tl * 4;

#pragma unroll
        for (int kh = 0; kh < 2; kh++) {
            const uint32_t ko = kh * 32;
            uint32_t a[4][4], bb[4][2];
#pragma unroll
            for (int mt = 0; mt < 4; mt++) {
                uint32_t r = aT + mt * (16 * SA * 2) + ko;
                a[mt][0] = lds32(r);
                a[mt][1] = lds32(r + 8 * SA * 2);
                a[mt][2] = lds32(r + 16);
                a[mt][3] = lds32(r + 8 * SA * 2 + 16);
            }
#pragma unroll
            for (int nt = 0; nt < 4; nt++) {
                uint32_t r = bT + nt * (8 * SA * 2) + ko;
                bb[nt][0] = lds32(r);
                bb[nt][1] = lds32(r + 16);
            }
#pragma unroll
            for (int mt = 0; mt < 4; mt++)
#pragma unroll
                for (int nt = 0; nt < 4; nt++)
                    mma16816(d[mt][nt], a[mt], bb[nt]);
        }
        __syncthreads();
    }

    float2 bias[4], w1c[4], w2c[4];
#pragma unroll
    for (int nt = 0; nt < 4; nt++) {
        int col = n0 + wn0 + nt * 8 + 2 * tl;
        bias[nt] = *(const float2*)(b + col);
        w1c[nt]  = *(const float2*)(a1w + col);
        w2c[nt]  = *(const float2*)(a2w + col);
    }

#pragma unroll
    for (int mt = 0; mt < 4; mt++) {
        int row0 = m0 + wm0 + mt * 16 + g;
        float s1r0 = 0.f, s2r0 = 0.f, s1r1 = 0.f, s2r1 = 0.f;
#pragma unroll
        for (int nt = 0; nt < 4; nt++) {
            int col = n0 + wn0 + nt * 8 + 2 * tl;
            float2 v0 = make_float2(d[mt][nt][0] + bias[nt].x,
                                    d[mt][nt][1] + bias[nt].y);
            float2 v1 = make_float2(d[mt][nt][2] + bias[nt].x,
                                    d[mt][nt][3] + bias[nt].y);
            *(float2*)(g_h + (size_t)row0 * DOUT + col) = v0;
            *(float2*)(g_h + (size_t)(row0 + 8) * DOUT + col) = v1;
            s1r0 = fmaf(v0.x, w1c[nt].x, fmaf(v0.y, w1c[nt].y, s1r0));
            s2r0 = fmaf(v0.x, w2c[nt].x, fmaf(v0.y, w2c[nt].y, s2r0));
            s1r1 = fmaf(v1.x, w1c[nt].x, fmaf(v1.y, w1c[nt].y, s1r1));
            s2r1 = fmaf(v1.x, w2c[nt].x, fmaf(v1.y, w2c[nt].y, s2r1));
        }
        atomicAdd(&g_g1[row0], s1r0);
        atomicAdd(&g_g2[row0], s2r0);
        atomicAdd(&g_g1[row0 + 8], s1r1);
        atomicAdd(&g_g2[row0 + 8], s2r1);
    }
}

// ---------------------------------------------------------------------------
// attn kernel (PDL secondary, R14 version verbatim): phase 1 scans adj into
// smem index lists; griddepcontrol.wait; phase 2 scores/softmax/aggregate.
// ---------------------------------------------------------------------------
__global__ void __launch_bounds__(256)
attn_kernel(const float* __restrict__ adj, float* __restrict__ out)
{
    __shared__ int   s_idx[MAXN];
    __shared__ float s_e[MAXN];
    __shared__ int   s_cnt;
    __shared__ float s_inv;

    const int i = blockIdx.x;
    const int t = threadIdx.x;

    if (t == 0) s_cnt = 0;
    __syncthreads();

    const float4* row = (const float4*)(adj + (size_t)i * N_NODES);

    // ---- phase 1: scan (independent of the GEMM) ----
#pragma unroll
    for (int u = 0; u < 8; u++) {
        int f = t + u * 256;
        float4 v = row[f];
        int jb = f << 2;
        if (v.x > 0.f) { int p = atomicAdd(&s_cnt, 1); if (p < MAXN) s_idx[p] = jb + 0; }
        if (v.y > 0.f) { int p = atomicAdd(&s_cnt, 1); if (p < MAXN) s_idx[p] = jb + 1; }
        if (v.z > 0.f) { int p = atomicAdd(&s_cnt, 1); if (p < MAXN) s_idx[p] = jb + 2; }
        if (v.w > 0.f) { int p = atomicAdd(&s_cnt, 1); if (p < MAXN) s_idx[p] = jb + 3; }
    }
    __syncthreads();

    // ---- wait for the GEMM's g_h / g_g1 / g_g2 ----
    asm volatile("griddepcontrol.wait;" ::: "memory");

    const int cnt = s_cnt < MAXN ? s_cnt : MAXN;

    if (cnt == 0) {
        float acc = 0.f;
        for (int r = 0; r < N_NODES; r++) acc += g_h[(size_t)r * DOUT + t];
        out[(size_t)i * DOUT + t] = acc * (1.f / (float)N_NODES);
        return;
    }

    // ---- phase 2: scores ----
    const float g2i = g_g2[i];
    for (int k = t; k < cnt; k += 256) {
        float s = g2i + g_g1[s_idx[k]];
        s_e[k] = s > 0.f ? s : 0.2f * s;
    }
    __syncthreads();

    if (t < 32) {
        float m = -INFINITY;
        for (int k = t; k < cnt; k += 32) m = fmaxf(m, s_e[k]);
#pragma unroll
        for (int o = 16; o; o >>= 1) m = fmaxf(m, __shfl_xor_sync(0xffffffffu, m, o));
        float ssum = 0.f;
        for (int k = t; k < cnt; k += 32) {
            float w = __expf(s_e[k] - m);
            s_e[k] = w;
            ssum += w;
        }
#pragma unroll
        for (int o = 16; o; o >>= 1) ssum += __shfl_xor_sync(0xffffffffu, ssum, o);
        if (t == 0) s_inv = 1.f / ssum;
    }
    __syncthreads();

    const float inv = s_inv;
    float a0 = 0.f, a1 = 0.f, a2 = 0.f, a3 = 0.f;
    int k = 0;
    for (; k + 4 <= cnt; k += 4) {
        a0 = fmaf(s_e[k + 0], g_h[(size_t)s_idx[k + 0] * DOUT + t], a0);
        a1 = fmaf(s_e[k + 1], g_h[(size_t)s_idx[k + 1] * DOUT + t], a1);
        a2 = fmaf(s_e[k + 2], g_h[(size_t)s_idx[k + 2] * DOUT + t], a2);
        a3 = fmaf(s_e[k + 3], g_h[(size_t)s_idx[k + 3] * DOUT + t], a3);
    }
    for (; k < cnt; k++)
        a0 = fmaf(s_e[k], g_h[(size_t)s_idx[k] * DOUT + t], a0);

    out[(size_t)i * DOUT + t] = (a0 + a1 + a2 + a3) * inv;
}

// ---------------------------------------------------------------------------
extern "C" void kernel_launch(void* const* d_in, const int* in_sizes, int n_in,
                              void* d_out, int out_size)
{
    const float* x   = (const float*)d_in[0];   // [8192, 512]
    const float* adj = (const float*)d_in[1];   // [8192, 8192]
    const float* W1  = (const float*)d_in[2];   // [512, 256]
    const float* b1  = (const float*)d_in[3];   // [256]
    const float* a1w = (const float*)d_in[4];   // [256]
    const float* a1b = (const float*)d_in[5];   // scalar
    const float* a2w = (const float*)d_in[6];   // [256]
    const float* a2b = (const float*)d_in[7];   // scalar
    float* out = (float*)d_out;                 // [8192, 256]

    static bool attr_set = false;
    if (!attr_set) {
        cudaFuncSetAttribute(gemm_mma_kernel,
                             cudaFuncAttributeMaxDynamicSharedMemorySize,
                             GEMM_SMEM);
        attr_set = true;
    }

    prep_kernel<<<PREP_BLOCKS, 256>>>(x, W1, a1b, a2b);
    dim3 gg(DOUT / 128, N_NODES / 128);         // (2, 64)
    gemm_mma_kernel<<<gg, 256, GEMM_SMEM>>>(b1, a1w, a2w);

    // attn via PDL: its scan phase overlaps the GEMM mainloop.
    cudaLaunchConfig_t cfg = {};
    cfg.gridDim  = dim3(N_NODES, 1, 1);
    cfg.blockDim = dim3(256, 1, 1);
    cfg.dynamicSmemBytes = 0;
    cfg.stream = 0;
    cudaLaunchAttribute attrs[1];
    attrs[0].id = cudaLaunchAttributeProgrammaticStreamSerialization;
    attrs[0].val.programmaticStreamSerializationAllowed = 1;
    cfg.attrs = attrs;
    cfg.numAttrs = 1;
    cudaLaunchKernelEx(&cfg, attn_kernel, adj, out);
}